// round 1
// baseline (speedup 1.0000x reference)
#include <cuda_runtime.h>
#include <cuda_bf16.h>
#include <math.h>

// Problem constants
#define BATCH 2
#define SEQ   2048
#define CMODEL 1024
#define NHEAD 16
#define HDIM  64
#define MROWS (BATCH * SEQ)   // 4096

// ---------------------------------------------------------------------------
// Scratch (no allocations allowed in kernel_launch)
// ---------------------------------------------------------------------------
__device__ float g_q[MROWS * CMODEL];
__device__ float g_k[MROWS * CMODEL];
__device__ float g_v[MROWS * CMODEL];
__device__ float g_attn[MROWS * CMODEL];

// ---------------------------------------------------------------------------
// SGEMM: C[m][n] = sum_k A[m][k] * W[n][k]   (A: [M,K] row-major, W: [N,K])
// Block tile 64x64, K-tile 16, 256 threads, 4x4 per-thread micro-tile.
// All dims are multiples of tile sizes (M=4096, N=K=1024), no bounds checks.
// ---------------------------------------------------------------------------
#define BM 64
#define BN 64
#define BK 16

__global__ __launch_bounds__(256) void sgemm_nt(const float* __restrict__ A,
                                                const float* __restrict__ W,
                                                float* __restrict__ C,
                                                int M, int N, int K) {
    __shared__ float As[BK][BM];
    __shared__ float Ws[BK][BN];

    const int tid = threadIdx.x;
    const int tx = tid % 16;          // micro-tile col group
    const int ty = tid / 16;          // micro-tile row group
    const int m0 = blockIdx.y * BM;
    const int n0 = blockIdx.x * BN;

    // loader mapping: 256 threads, each loads one float4 of A-tile and W-tile
    const int lrow = tid / 4;         // 0..63
    const int lcol = (tid % 4) * 4;   // 0,4,8,12

    float acc[4][4];
#pragma unroll
    for (int i = 0; i < 4; i++)
#pragma unroll
        for (int j = 0; j < 4; j++) acc[i][j] = 0.0f;

    for (int k0 = 0; k0 < K; k0 += BK) {
        float4 a = *reinterpret_cast<const float4*>(&A[(size_t)(m0 + lrow) * K + k0 + lcol]);
        float4 w = *reinterpret_cast<const float4*>(&W[(size_t)(n0 + lrow) * K + k0 + lcol]);
        As[lcol + 0][lrow] = a.x; As[lcol + 1][lrow] = a.y;
        As[lcol + 2][lrow] = a.z; As[lcol + 3][lrow] = a.w;
        Ws[lcol + 0][lrow] = w.x; Ws[lcol + 1][lrow] = w.y;
        Ws[lcol + 2][lrow] = w.z; Ws[lcol + 3][lrow] = w.w;
        __syncthreads();

#pragma unroll
        for (int k = 0; k < BK; k++) {
            float av[4], wv[4];
#pragma unroll
            for (int i = 0; i < 4; i++) av[i] = As[k][ty * 4 + i];
#pragma unroll
            for (int j = 0; j < 4; j++) wv[j] = Ws[k][tx * 4 + j];
#pragma unroll
            for (int i = 0; i < 4; i++)
#pragma unroll
                for (int j = 0; j < 4; j++) acc[i][j] = fmaf(av[i], wv[j], acc[i][j]);
        }
        __syncthreads();
    }

#pragma unroll
    for (int i = 0; i < 4; i++) {
        float4 out;
        out.x = acc[i][0]; out.y = acc[i][1]; out.z = acc[i][2]; out.w = acc[i][3];
        *reinterpret_cast<float4*>(&C[(size_t)(m0 + ty * 4 + i) * N + n0 + tx * 4]) = out;
    }
}

// ---------------------------------------------------------------------------
// RoPE: applied in-place to Q and K.
// Layout: [B, T, H, HDIM] contiguous (== [B,T,C]). freqs_cis: [T, HDIM/2, 2].
// One thread per rotation pair; handles both Q and K.
// ---------------------------------------------------------------------------
__global__ void rope_kernel(float* __restrict__ q, float* __restrict__ k,
                            const float* __restrict__ freqs) {
    const int HALF = HDIM / 2;  // 32
    long long p = (long long)blockIdx.x * blockDim.x + threadIdx.x;
    const long long total = (long long)BATCH * SEQ * NHEAD * HALF;
    if (p >= total) return;

    int d2 = (int)(p % HALF);
    int h  = (int)((p / HALF) % NHEAD);
    int t  = (int)((p / (HALF * NHEAD)) % SEQ);
    int b  = (int)(p / ((long long)HALF * NHEAD * SEQ));

    float c = freqs[t * HDIM + d2 * 2 + 0];
    float s = freqs[t * HDIM + d2 * 2 + 1];

    size_t base = (((size_t)b * SEQ + t) * NHEAD + h) * HDIM + d2 * 2;

    float q0 = q[base], q1 = q[base + 1];
    q[base]     = q0 * c - q1 * s;
    q[base + 1] = q0 * s + q1 * c;

    float k0 = k[base], k1 = k[base + 1];
    k[base]     = k0 * c - k1 * s;
    k[base + 1] = k0 * s + k1 * c;
}

// ---------------------------------------------------------------------------
// Flash-attention (fp32, causal). Thread-per-query, 128 queries / block,
// 32-key shared tiles of K and V. Online softmax in registers.
// ---------------------------------------------------------------------------
#define QB 128
#define KB 32

__global__ __launch_bounds__(128) void flash_attn(const float* __restrict__ Q,
                                                  const float* __restrict__ K,
                                                  const float* __restrict__ V,
                                                  float* __restrict__ O) {
    const int qb = blockIdx.x;
    const int h  = blockIdx.y;
    const int b  = blockIdx.z;
    const int qi = qb * QB + threadIdx.x;   // global query index (0..SEQ-1)

    __shared__ float Ks[KB][HDIM];
    __shared__ float Vs[KB][HDIM];

    const float scale = 0.125f;             // 1/sqrt(64)

    // load this thread's query (pre-scaled)
    float qreg[HDIM];
    {
        const float* qptr = Q + (((size_t)b * SEQ + qi) * NHEAD + h) * HDIM;
#pragma unroll
        for (int d = 0; d < HDIM; d += 4) {
            float4 v4 = *reinterpret_cast<const float4*>(qptr + d);
            qreg[d]     = v4.x * scale;
            qreg[d + 1] = v4.y * scale;
            qreg[d + 2] = v4.z * scale;
            qreg[d + 3] = v4.w * scale;
        }
    }

    float acc[HDIM];
#pragma unroll
    for (int d = 0; d < HDIM; d++) acc[d] = 0.0f;
    float m = -1e30f, l = 0.0f;

    const int kend = (qb + 1) * QB;   // exclusive key bound for this block

    for (int kt = 0; kt < kend; kt += KB) {
        // cooperative tile load: KB*HDIM floats = 512 float4, 128 threads -> 4 each
        for (int i = threadIdx.x; i < KB * (HDIM / 4); i += 128) {
            int r  = i / (HDIM / 4);
            int c4 = (i % (HDIM / 4)) * 4;
            size_t src = (((size_t)b * SEQ + kt + r) * NHEAD + h) * HDIM + c4;
            *reinterpret_cast<float4*>(&Ks[r][c4]) = *reinterpret_cast<const float4*>(&K[src]);
            *reinterpret_cast<float4*>(&Vs[r][c4]) = *reinterpret_cast<const float4*>(&V[src]);
        }
        __syncthreads();

        if (kt <= qi) {   // tile has at least one unmasked key for this query
            float s[KB];
            float tmax = -1e30f;
#pragma unroll
            for (int j = 0; j < KB; j++) {
                float dot = 0.0f;
#pragma unroll
                for (int d = 0; d < HDIM; d++) dot = fmaf(qreg[d], Ks[j][d], dot);
                s[j] = (kt + j <= qi) ? dot : -1e30f;
                tmax = fmaxf(tmax, s[j]);
            }
            float m_new = fmaxf(m, tmax);
            float corr = __expf(m - m_new);
            l *= corr;
#pragma unroll
            for (int d = 0; d < HDIM; d++) acc[d] *= corr;
#pragma unroll
            for (int j = 0; j < KB; j++) {
                float p = __expf(s[j] - m_new);
                l += p;
#pragma unroll
                for (int d = 0; d < HDIM; d++) acc[d] = fmaf(p, Vs[j][d], acc[d]);
            }
            m = m_new;
        }
        __syncthreads();
    }

    const float inv = 1.0f / l;
    float* optr = O + (((size_t)b * SEQ + qi) * NHEAD + h) * HDIM;
#pragma unroll
    for (int d = 0; d < HDIM; d += 4) {
        float4 v4;
        v4.x = acc[d] * inv; v4.y = acc[d + 1] * inv;
        v4.z = acc[d + 2] * inv; v4.w = acc[d + 3] * inv;
        *reinterpret_cast<float4*>(optr + d) = v4;
    }
}

// ---------------------------------------------------------------------------
// kernel_launch
// ---------------------------------------------------------------------------
extern "C" void kernel_launch(void* const* d_in, const int* in_sizes, int n_in,
                              void* d_out, int out_size) {
    const float* x     = (const float*)d_in[0];
    const float* freqs = (const float*)d_in[1];
    const float* Wq    = (const float*)d_in[2];
    const float* Wk    = (const float*)d_in[3];
    const float* Wv    = (const float*)d_in[4];
    const float* Wo    = (const float*)d_in[5];
    float* out = (float*)d_out;

    float* q = nullptr; float* k = nullptr; float* v = nullptr; float* attn = nullptr;
    cudaGetSymbolAddress((void**)&q,    g_q);
    cudaGetSymbolAddress((void**)&k,    g_k);
    cudaGetSymbolAddress((void**)&v,    g_v);
    cudaGetSymbolAddress((void**)&attn, g_attn);

    dim3 ggrid(CMODEL / BN, MROWS / BM);
    sgemm_nt<<<ggrid, 256>>>(x, Wq, q, MROWS, CMODEL, CMODEL);
    sgemm_nt<<<ggrid, 256>>>(x, Wk, k, MROWS, CMODEL, CMODEL);
    sgemm_nt<<<ggrid, 256>>>(x, Wv, v, MROWS, CMODEL, CMODEL);

    {
        long long total = (long long)BATCH * SEQ * NHEAD * (HDIM / 2);
        int threads = 256;
        int blocks = (int)((total + threads - 1) / threads);
        rope_kernel<<<blocks, threads>>>(q, k, freqs);
    }

    {
        dim3 agrid(SEQ / QB, NHEAD, BATCH);
        flash_attn<<<agrid, 128>>>(q, k, v, attn);
    }

    sgemm_nt<<<ggrid, 256>>>(attn, Wo, out, MROWS, CMODEL, CMODEL);
}

// round 3
// speedup vs baseline: 1.3754x; 1.3754x over previous
#include <cuda_runtime.h>
#include <cuda_bf16.h>
#include <cstdint>
#include <math.h>

// Problem constants
#define BATCH 2
#define SEQ   2048
#define CMODEL 1024
#define NHEAD 16
#define HDIM  64
#define MROWS (BATCH * SEQ)   // 4096

// ---------------------------------------------------------------------------
// Scratch
// ---------------------------------------------------------------------------
__device__ float g_q[MROWS * CMODEL];
__device__ float g_k[MROWS * CMODEL];
__device__ float g_v[MROWS * CMODEL];
__device__ float g_attn[MROWS * CMODEL];

// ---------------------------------------------------------------------------
// Helpers
// ---------------------------------------------------------------------------
__device__ __forceinline__ uint32_t smem_u32(const void* p) {
    uint32_t a;
    asm("{ .reg .u64 t; cvta.to.shared.u64 t, %1; cvt.u32.u64 %0, t; }" : "=r"(a) : "l"(p));
    return a;
}
__device__ __forceinline__ void cp_async16(uint32_t s, const void* g) {
    asm volatile("cp.async.ca.shared.global [%0], [%1], 16;" :: "r"(s), "l"(g));
}
#define CP_COMMIT()  asm volatile("cp.async.commit_group;" ::: "memory")
#define CP_WAIT(N)   asm volatile("cp.async.wait_group %0;" :: "n"(N) : "memory")

__device__ __forceinline__ uint32_t f2tf32(float f) {
    uint32_t u;
    asm("cvt.rna.tf32.f32 %0, %1;" : "=r"(u) : "f"(f));
    return u;
}
__device__ __forceinline__ void mma_tf32(float (&d)[4], const uint32_t (&a)[4],
                                         const uint32_t (&b)[2]) {
    asm volatile(
        "mma.sync.aligned.m16n8k8.row.col.f32.tf32.tf32.f32 "
        "{%0,%1,%2,%3}, {%4,%5,%6,%7}, {%8,%9}, {%0,%1,%2,%3};"
        : "+f"(d[0]), "+f"(d[1]), "+f"(d[2]), "+f"(d[3])
        : "r"(a[0]), "r"(a[1]), "r"(a[2]), "r"(a[3]), "r"(b[0]), "r"(b[1]));
}

// ---------------------------------------------------------------------------
// TF32 mma.sync GEMM: C[m][n] = sum_k A[m][k] * W[n][k]
// A:[M,K] row-major, W:[N,K] row-major. CTA tile 128x128, BK=32,
// 256 threads = 8 warps in 4(M) x 2(N); warp tile 32x64.
// cp.async double-buffered SMEM, padded stride to kill bank conflicts.
// ---------------------------------------------------------------------------
#define BM 128
#define BN 128
#define BK 32
#define KSTRIDE (BK + 4)   // 36 floats per row
#define TILE_FLOATS (BM * KSTRIDE)
#define GSMEM_FLOATS (4 * TILE_FLOATS)   // 2 stages x (A + W)

__global__ __launch_bounds__(256) void gemm_tf32mma(const float* __restrict__ A,
                                                    const float* __restrict__ W,
                                                    float* __restrict__ C,
                                                    int K, int N) {
    extern __shared__ float smem[];
    // layout: [stage][A|W][BM][KSTRIDE]
    float* As[2] = { smem,                   smem + 2 * TILE_FLOATS };
    float* Ws[2] = { smem + TILE_FLOATS,     smem + 3 * TILE_FLOATS };

    const int tid  = threadIdx.x;
    const int lane = tid & 31;
    const int wid  = tid >> 5;
    const int g    = lane >> 2;       // groupID 0..7
    const int tg   = lane & 3;        // thread-in-group
    const int wm   = (wid & 3) * 32;  // warp M offset in CTA tile
    const int wn   = (wid >> 2) * 64; // warp N offset in CTA tile
    const int m0   = blockIdx.y * BM;
    const int n0   = blockIdx.x * BN;

    // loader mapping: thread t -> row t>>1, 16-float half-row (t&1)
    const int lrow = tid >> 1;
    const int lcol = (tid & 1) * 16;
    const float* agp = &A[(size_t)(m0 + lrow) * K + lcol];
    const float* wgp = &W[(size_t)(n0 + lrow) * K + lcol];
    const uint32_t asp0 = smem_u32(&As[0][lrow * KSTRIDE + lcol]);
    const uint32_t wsp0 = smem_u32(&Ws[0][lrow * KSTRIDE + lcol]);
    const uint32_t stage_bytes = 2 * TILE_FLOATS * 4;

    float acc[2][8][4];
#pragma unroll
    for (int mt = 0; mt < 2; mt++)
#pragma unroll
        for (int nt = 0; nt < 8; nt++)
#pragma unroll
            for (int r = 0; r < 4; r++) acc[mt][nt][r] = 0.0f;

    const int ntiles = K / BK;

    // prefetch tile 0 into stage 0
#pragma unroll
    for (int j = 0; j < 4; j++) {
        cp_async16(asp0 + j * 16, agp + j * 4);
        cp_async16(wsp0 + j * 16, wgp + j * 4);
    }
    CP_COMMIT();

    for (int kt = 0; kt < ntiles; kt++) {
        const int buf = kt & 1;
        if (kt + 1 < ntiles) {
            const int nb = (kt + 1) & 1;
            const int ko = (kt + 1) * BK;
#pragma unroll
            for (int j = 0; j < 4; j++) {
                cp_async16(asp0 + nb * stage_bytes + j * 16, agp + ko + j * 4);
                cp_async16(wsp0 + nb * stage_bytes + j * 16, wgp + ko + j * 4);
            }
            CP_COMMIT();
            CP_WAIT(1);
        } else {
            CP_WAIT(0);
        }
        __syncthreads();

        const float* at = As[buf];
        const float* wt = Ws[buf];
#pragma unroll
        for (int ks = 0; ks < 4; ks++) {
            const int kc = ks * 8 + tg;
            uint32_t a[2][4];
#pragma unroll
            for (int mt = 0; mt < 2; mt++) {
                const int r0 = (wm + mt * 16 + g) * KSTRIDE;
                a[mt][0] = f2tf32(at[r0 + kc]);
                a[mt][1] = f2tf32(at[r0 + 8 * KSTRIDE + kc]);
                a[mt][2] = f2tf32(at[r0 + kc + 4]);
                a[mt][3] = f2tf32(at[r0 + 8 * KSTRIDE + kc + 4]);
            }
            uint32_t b[8][2];
#pragma unroll
            for (int nt = 0; nt < 8; nt++) {
                const int r0 = (wn + nt * 8 + g) * KSTRIDE;
                b[nt][0] = f2tf32(wt[r0 + kc]);
                b[nt][1] = f2tf32(wt[r0 + kc + 4]);
            }
#pragma unroll
            for (int mt = 0; mt < 2; mt++)
#pragma unroll
                for (int nt = 0; nt < 8; nt++)
                    mma_tf32(acc[mt][nt], a[mt], b[nt]);
        }
        __syncthreads();
    }

    // epilogue: c0,c1 -> (row, col..col+1); c2,c3 -> (row+8, ...)
#pragma unroll
    for (int mt = 0; mt < 2; mt++) {
        const int row = m0 + wm + mt * 16 + g;
#pragma unroll
        for (int nt = 0; nt < 8; nt++) {
            const int col = n0 + wn + nt * 8 + 2 * tg;
            float2 v0 = make_float2(acc[mt][nt][0], acc[mt][nt][1]);
            float2 v1 = make_float2(acc[mt][nt][2], acc[mt][nt][3]);
            *reinterpret_cast<float2*>(&C[(size_t)row * N + col]) = v0;
            *reinterpret_cast<float2*>(&C[(size_t)(row + 8) * N + col]) = v1;
        }
    }
}

// ---------------------------------------------------------------------------
// RoPE (unchanged)
// ---------------------------------------------------------------------------
__global__ void rope_kernel(float* __restrict__ q, float* __restrict__ k,
                            const float* __restrict__ freqs) {
    const int HALF = HDIM / 2;
    long long p = (long long)blockIdx.x * blockDim.x + threadIdx.x;
    const long long total = (long long)BATCH * SEQ * NHEAD * HALF;
    if (p >= total) return;

    int d2 = (int)(p % HALF);
    int h  = (int)((p / HALF) % NHEAD);
    int t  = (int)((p / (HALF * NHEAD)) % SEQ);
    int b  = (int)(p / ((long long)HALF * NHEAD * SEQ));

    float c = freqs[t * HDIM + d2 * 2 + 0];
    float s = freqs[t * HDIM + d2 * 2 + 1];

    size_t base = (((size_t)b * SEQ + t) * NHEAD + h) * HDIM + d2 * 2;

    float q0 = q[base], q1 = q[base + 1];
    q[base]     = q0 * c - q1 * s;
    q[base + 1] = q0 * s + q1 * c;

    float k0 = k[base], k1 = k[base + 1];
    k[base]     = k0 * c - k1 * s;
    k[base + 1] = k0 * s + k1 * c;
}

// ---------------------------------------------------------------------------
// Flash-attention (unchanged from passing R1)
// ---------------------------------------------------------------------------
#define QB 128
#define KB 32

__global__ __launch_bounds__(128) void flash_attn(const float* __restrict__ Q,
                                                  const float* __restrict__ K,
                                                  const float* __restrict__ V,
                                                  float* __restrict__ O) {
    const int qb = blockIdx.x;
    const int h  = blockIdx.y;
    const int b  = blockIdx.z;
    const int qi = qb * QB + threadIdx.x;

    __shared__ float Ks[KB][HDIM];
    __shared__ float Vs[KB][HDIM];

    const float scale = 0.125f;

    float qreg[HDIM];
    {
        const float* qptr = Q + (((size_t)b * SEQ + qi) * NHEAD + h) * HDIM;
#pragma unroll
        for (int d = 0; d < HDIM; d += 4) {
            float4 v4 = *reinterpret_cast<const float4*>(qptr + d);
            qreg[d]     = v4.x * scale;
            qreg[d + 1] = v4.y * scale;
            qreg[d + 2] = v4.z * scale;
            qreg[d + 3] = v4.w * scale;
        }
    }

    float acc[HDIM];
#pragma unroll
    for (int d = 0; d < HDIM; d++) acc[d] = 0.0f;
    float m = -1e30f, l = 0.0f;

    const int kend = (qb + 1) * QB;

    for (int kt = 0; kt < kend; kt += KB) {
        for (int i = threadIdx.x; i < KB * (HDIM / 4); i += 128) {
            int r  = i / (HDIM / 4);
            int c4 = (i % (HDIM / 4)) * 4;
            size_t src = (((size_t)b * SEQ + kt + r) * NHEAD + h) * HDIM + c4;
            *reinterpret_cast<float4*>(&Ks[r][c4]) = *reinterpret_cast<const float4*>(&K[src]);
            *reinterpret_cast<float4*>(&Vs[r][c4]) = *reinterpret_cast<const float4*>(&V[src]);
        }
        __syncthreads();

        if (kt <= qi) {
            float s[KB];
            float tmax = -1e30f;
#pragma unroll
            for (int j = 0; j < KB; j++) {
                float dot = 0.0f;
#pragma unroll
                for (int d = 0; d < HDIM; d++) dot = fmaf(qreg[d], Ks[j][d], dot);
                s[j] = (kt + j <= qi) ? dot : -1e30f;
                tmax = fmaxf(tmax, s[j]);
            }
            float m_new = fmaxf(m, tmax);
            float corr = __expf(m - m_new);
            l *= corr;
#pragma unroll
            for (int d = 0; d < HDIM; d++) acc[d] *= corr;
#pragma unroll
            for (int j = 0; j < KB; j++) {
                float p = __expf(s[j] - m_new);
                l += p;
#pragma unroll
                for (int d = 0; d < HDIM; d++) acc[d] = fmaf(p, Vs[j][d], acc[d]);
            }
            m = m_new;
        }
        __syncthreads();
    }

    const float inv = 1.0f / l;
    float* optr = O + (((size_t)b * SEQ + qi) * NHEAD + h) * HDIM;
#pragma unroll
    for (int d = 0; d < HDIM; d += 4) {
        float4 v4;
        v4.x = acc[d] * inv; v4.y = acc[d + 1] * inv;
        v4.z = acc[d + 2] * inv; v4.w = acc[d + 3] * inv;
        *reinterpret_cast<float4*>(optr + d) = v4;
    }
}

// ---------------------------------------------------------------------------
// kernel_launch
// ---------------------------------------------------------------------------
extern "C" void kernel_launch(void* const* d_in, const int* in_sizes, int n_in,
                              void* d_out, int out_size) {
    const float* x     = (const float*)d_in[0];
    const float* freqs = (const float*)d_in[1];
    const float* Wq    = (const float*)d_in[2];
    const float* Wk    = (const float*)d_in[3];
    const float* Wv    = (const float*)d_in[4];
    const float* Wo    = (const float*)d_in[5];
    float* out = (float*)d_out;

    float* q = nullptr; float* k = nullptr; float* v = nullptr; float* attn = nullptr;
    cudaGetSymbolAddress((void**)&q,    g_q);
    cudaGetSymbolAddress((void**)&k,    g_k);
    cudaGetSymbolAddress((void**)&v,    g_v);
    cudaGetSymbolAddress((void**)&attn, g_attn);

    const int smem_bytes = GSMEM_FLOATS * sizeof(float);   // 73728
    cudaFuncSetAttribute(gemm_tf32mma, cudaFuncAttributeMaxDynamicSharedMemorySize, smem_bytes);

    dim3 ggrid(CMODEL / BN, MROWS / BM);
    gemm_tf32mma<<<ggrid, 256, smem_bytes>>>(x, Wq, q, CMODEL, CMODEL);
    gemm_tf32mma<<<ggrid, 256, smem_bytes>>>(x, Wk, k, CMODEL, CMODEL);
    gemm_tf32mma<<<ggrid, 256, smem_bytes>>>(x, Wv, v, CMODEL, CMODEL);

    {
        long long total = (long long)BATCH * SEQ * NHEAD * (HDIM / 2);
        int threads = 256;
        int blocks = (int)((total + threads - 1) / threads);
        rope_kernel<<<blocks, threads>>>(q, k, freqs);
    }

    {
        dim3 agrid(SEQ / QB, NHEAD, BATCH);
        flash_attn<<<agrid, 128>>>(q, k, v, attn);
    }

    gemm_tf32mma<<<ggrid, 256, smem_bytes>>>(attn, Wo, out, CMODEL, CMODEL);
}

// round 4
// speedup vs baseline: 2.5667x; 1.8661x over previous
#include <cuda_runtime.h>
#include <cuda_bf16.h>
#include <cstdint>
#include <math.h>

// Problem constants
#define BATCH 2
#define SEQ   2048
#define CMODEL 1024
#define NHEAD 16
#define HDIM  64
#define MROWS (BATCH * SEQ)   // 4096

// ---------------------------------------------------------------------------
// Scratch
// ---------------------------------------------------------------------------
__device__ float g_q[MROWS * CMODEL];
__device__ float g_k[MROWS * CMODEL];
__device__ float g_v[MROWS * CMODEL];
__device__ float g_attn[MROWS * CMODEL];

// ---------------------------------------------------------------------------
// Helpers
// ---------------------------------------------------------------------------
__device__ __forceinline__ uint32_t smem_u32(const void* p) {
    uint32_t a;
    asm("{ .reg .u64 t; cvta.to.shared.u64 t, %1; cvt.u32.u64 %0, t; }" : "=r"(a) : "l"(p));
    return a;
}
__device__ __forceinline__ void cp_async16(uint32_t s, const void* g) {
    asm volatile("cp.async.ca.shared.global [%0], [%1], 16;" :: "r"(s), "l"(g));
}
#define CP_COMMIT()  asm volatile("cp.async.commit_group;" ::: "memory")
#define CP_WAIT(N)   asm volatile("cp.async.wait_group %0;" :: "n"(N) : "memory")

__device__ __forceinline__ uint32_t f2tf32(float f) {
    uint32_t u;
    asm("cvt.rna.tf32.f32 %0, %1;" : "=r"(u) : "f"(f));
    return u;
}
__device__ __forceinline__ void mma_tf32(float (&d)[4], const uint32_t (&a)[4],
                                         const uint32_t (&b)[2]) {
    asm volatile(
        "mma.sync.aligned.m16n8k8.row.col.f32.tf32.tf32.f32 "
        "{%0,%1,%2,%3}, {%4,%5,%6,%7}, {%8,%9}, {%0,%1,%2,%3};"
        : "+f"(d[0]), "+f"(d[1]), "+f"(d[2]), "+f"(d[3])
        : "r"(a[0]), "r"(a[1]), "r"(a[2]), "r"(a[3]), "r"(b[0]), "r"(b[1]));
}

// ---------------------------------------------------------------------------
// TF32 mma.sync GEMM (unchanged from R3, passing)
// ---------------------------------------------------------------------------
#define BM 128
#define BN 128
#define BK 32
#define KSTRIDE (BK + 4)
#define TILE_FLOATS (BM * KSTRIDE)
#define GSMEM_FLOATS (4 * TILE_FLOATS)

__global__ __launch_bounds__(256) void gemm_tf32mma(const float* __restrict__ A,
                                                    const float* __restrict__ W,
                                                    float* __restrict__ C,
                                                    int K, int N) {
    extern __shared__ float smem[];
    float* As[2] = { smem,               smem + 2 * TILE_FLOATS };
    float* Ws[2] = { smem + TILE_FLOATS, smem + 3 * TILE_FLOATS };

    const int tid  = threadIdx.x;
    const int lane = tid & 31;
    const int wid  = tid >> 5;
    const int g    = lane >> 2;
    const int tg   = lane & 3;
    const int wm   = (wid & 3) * 32;
    const int wn   = (wid >> 2) * 64;
    const int m0   = blockIdx.y * BM;
    const int n0   = blockIdx.x * BN;

    const int lrow = tid >> 1;
    const int lcol = (tid & 1) * 16;
    const float* agp = &A[(size_t)(m0 + lrow) * K + lcol];
    const float* wgp = &W[(size_t)(n0 + lrow) * K + lcol];
    const uint32_t asp0 = smem_u32(&As[0][lrow * KSTRIDE + lcol]);
    const uint32_t wsp0 = smem_u32(&Ws[0][lrow * KSTRIDE + lcol]);
    const uint32_t stage_bytes = 2 * TILE_FLOATS * 4;

    float acc[2][8][4];
#pragma unroll
    for (int mt = 0; mt < 2; mt++)
#pragma unroll
        for (int nt = 0; nt < 8; nt++)
#pragma unroll
            for (int r = 0; r < 4; r++) acc[mt][nt][r] = 0.0f;

    const int ntiles = K / BK;

#pragma unroll
    for (int j = 0; j < 4; j++) {
        cp_async16(asp0 + j * 16, agp + j * 4);
        cp_async16(wsp0 + j * 16, wgp + j * 4);
    }
    CP_COMMIT();

    for (int kt = 0; kt < ntiles; kt++) {
        const int buf = kt & 1;
        if (kt + 1 < ntiles) {
            const int nb = (kt + 1) & 1;
            const int ko = (kt + 1) * BK;
#pragma unroll
            for (int j = 0; j < 4; j++) {
                cp_async16(asp0 + nb * stage_bytes + j * 16, agp + ko + j * 4);
                cp_async16(wsp0 + nb * stage_bytes + j * 16, wgp + ko + j * 4);
            }
            CP_COMMIT();
            CP_WAIT(1);
        } else {
            CP_WAIT(0);
        }
        __syncthreads();

        const float* at = As[buf];
        const float* wt = Ws[buf];
#pragma unroll
        for (int ks = 0; ks < 4; ks++) {
            const int kc = ks * 8 + tg;
            uint32_t a[2][4];
#pragma unroll
            for (int mt = 0; mt < 2; mt++) {
                const int r0 = (wm + mt * 16 + g) * KSTRIDE;
                a[mt][0] = f2tf32(at[r0 + kc]);
                a[mt][1] = f2tf32(at[r0 + 8 * KSTRIDE + kc]);
                a[mt][2] = f2tf32(at[r0 + kc + 4]);
                a[mt][3] = f2tf32(at[r0 + 8 * KSTRIDE + kc + 4]);
            }
            uint32_t b[8][2];
#pragma unroll
            for (int nt = 0; nt < 8; nt++) {
                const int r0 = (wn + nt * 8 + g) * KSTRIDE;
                b[nt][0] = f2tf32(wt[r0 + kc]);
                b[nt][1] = f2tf32(wt[r0 + kc + 4]);
            }
#pragma unroll
            for (int mt = 0; mt < 2; mt++)
#pragma unroll
                for (int nt = 0; nt < 8; nt++)
                    mma_tf32(acc[mt][nt], a[mt], b[nt]);
        }
        __syncthreads();
    }

#pragma unroll
    for (int mt = 0; mt < 2; mt++) {
        const int row = m0 + wm + mt * 16 + g;
#pragma unroll
        for (int nt = 0; nt < 8; nt++) {
            const int col = n0 + wn + nt * 8 + 2 * tg;
            float2 v0 = make_float2(acc[mt][nt][0], acc[mt][nt][1]);
            float2 v1 = make_float2(acc[mt][nt][2], acc[mt][nt][3]);
            *reinterpret_cast<float2*>(&C[(size_t)row * N + col]) = v0;
            *reinterpret_cast<float2*>(&C[(size_t)(row + 8) * N + col]) = v1;
        }
    }
}

// ---------------------------------------------------------------------------
// RoPE (unchanged)
// ---------------------------------------------------------------------------
__global__ void rope_kernel(float* __restrict__ q, float* __restrict__ k,
                            const float* __restrict__ freqs) {
    const int HALF = HDIM / 2;
    long long p = (long long)blockIdx.x * blockDim.x + threadIdx.x;
    const long long total = (long long)BATCH * SEQ * NHEAD * HALF;
    if (p >= total) return;

    int d2 = (int)(p % HALF);
    int h  = (int)((p / HALF) % NHEAD);
    int t  = (int)((p / (HALF * NHEAD)) % SEQ);
    int b  = (int)(p / ((long long)HALF * NHEAD * SEQ));

    float c = freqs[t * HDIM + d2 * 2 + 0];
    float s = freqs[t * HDIM + d2 * 2 + 1];

    size_t base = (((size_t)b * SEQ + t) * NHEAD + h) * HDIM + d2 * 2;

    float q0 = q[base], q1 = q[base + 1];
    q[base]     = q0 * c - q1 * s;
    q[base + 1] = q0 * s + q1 * c;

    float k0 = k[base], k1 = k[base + 1];
    k[base]     = k0 * c - k1 * s;
    k[base + 1] = k0 * s + k1 * c;
}

// ---------------------------------------------------------------------------
// Tensor-core flash-attention (tf32 mma.sync), causal.
// CTA: 128 queries x 1 head. 8 warps x 16 query rows. Key tiles of 64.
// K/V tiles double-buffered via cp.async; P routed through per-warp SMEM.
// ---------------------------------------------------------------------------
#define APAD 68                      // padded row stride (floats)
#define ATILE (64 * APAD)            // 4352 floats per K or V tile
#define ASMEM_FLOATS (4 * ATILE + 128 * APAD)   // 2 stages x (K+V) + P

__global__ __launch_bounds__(256, 1) void flash_attn_mma(const float* __restrict__ Q,
                                                         const float* __restrict__ K,
                                                         const float* __restrict__ V,
                                                         float* __restrict__ O) {
    extern __shared__ float sm[];
    float* Ksm[2] = { sm,             sm + 2 * ATILE };
    float* Vsm[2] = { sm + ATILE,     sm + 3 * ATILE };
    float* Ps = sm + 4 * ATILE;

    const int tid  = threadIdx.x;
    const int lane = tid & 31;
    const int wid  = tid >> 5;       // 0..7
    const int g    = lane >> 2;      // 0..7
    const int tg   = lane & 3;       // 0..3

    const int qb = (int)gridDim.x - 1 - (int)blockIdx.x;  // long CTAs first
    const int h  = blockIdx.y;
    const int b  = blockIdx.z;
    const int q0 = qb * 128;
    const int wrow = wid * 16;
    const int r0g = q0 + wrow + g;       // this thread's two query rows
    const int r1g = r0g + 8;

    // ---- Q fragments (pre-scaled, tf32) ----
    const float scale = 0.125f;
    uint32_t qf[8][4];
    {
        const float* q0p = Q + (((size_t)b * SEQ + r0g) * NHEAD + h) * HDIM;
        const float* q1p = Q + (((size_t)b * SEQ + r1g) * NHEAD + h) * HDIM;
#pragma unroll
        for (int ks = 0; ks < 8; ks++) {
            const int kc = ks * 8 + tg;
            qf[ks][0] = f2tf32(q0p[kc] * scale);
            qf[ks][1] = f2tf32(q1p[kc] * scale);
            qf[ks][2] = f2tf32(q0p[kc + 4] * scale);
            qf[ks][3] = f2tf32(q1p[kc + 4] * scale);
        }
    }

    float of[8][4];
#pragma unroll
    for (int nt = 0; nt < 8; nt++)
#pragma unroll
        for (int r = 0; r < 4; r++) of[nt][r] = 0.0f;
    float mrow[2] = { -1e30f, -1e30f };
    float lrow[2] = { 0.0f, 0.0f };

    const int ntiles = (q0 + 128) / 64;

    // cp.async loader for key tile t into stage s
    const uint32_t ks0 = smem_u32(Ksm[0]);
    const uint32_t vs0 = smem_u32(Vsm[0]);
    const uint32_t stageB = 2 * ATILE * 4;

    auto prefetch = [&](int t, int s) {
        const int kt = t * 64;
#pragma unroll
        for (int i = 0; i < 4; i++) {
            const int f = tid + 256 * i;       // 0..1023
            const int row = f >> 4;
            const int c4 = (f & 15) * 4;
            const size_t gsrc = (((size_t)b * SEQ + kt + row) * NHEAD + h) * HDIM + c4;
            const uint32_t soff = s * stageB + (row * APAD + c4) * 4;
            cp_async16(ks0 + soff, &K[gsrc]);
            cp_async16(vs0 + soff, &V[gsrc]);
        }
    };

    prefetch(0, 0);
    CP_COMMIT();

    for (int t = 0; t < ntiles; t++) {
        const int kt = t * 64;
        if (t + 1 < ntiles) {
            prefetch(t + 1, (t + 1) & 1);
            CP_COMMIT();
            CP_WAIT(1);
        } else {
            CP_WAIT(0);
        }
        __syncthreads();

        const bool skip = kt > q0 + wrow + 15;   // tile fully above diagonal for this warp
        if (!skip) {
            const float* kb = Ksm[t & 1];
            const float* vb = Vsm[t & 1];

            // ---- S = Q * K^T ----
            float sacc[8][4];
#pragma unroll
            for (int nt = 0; nt < 8; nt++)
#pragma unroll
                for (int r = 0; r < 4; r++) sacc[nt][r] = 0.0f;

#pragma unroll
            for (int ks = 0; ks < 8; ks++) {
                const int kc = ks * 8 + tg;
#pragma unroll
                for (int nt = 0; nt < 8; nt++) {
                    uint32_t bf[2];
                    bf[0] = f2tf32(kb[(nt * 8 + g) * APAD + kc]);
                    bf[1] = f2tf32(kb[(nt * 8 + g) * APAD + kc + 4]);
                    mma_tf32(sacc[nt], qf[ks], bf);
                }
            }

            // ---- causal mask (only tiles that can touch the diagonal) ----
            if (kt + 63 > q0 + wrow) {
#pragma unroll
                for (int nt = 0; nt < 8; nt++) {
                    const int c = kt + nt * 8 + 2 * tg;
                    if (c > r0g)     sacc[nt][0] = -1e30f;
                    if (c + 1 > r0g) sacc[nt][1] = -1e30f;
                    if (c > r1g)     sacc[nt][2] = -1e30f;
                    if (c + 1 > r1g) sacc[nt][3] = -1e30f;
                }
            }

            // ---- online softmax ----
            float rmax0 = -1e30f, rmax1 = -1e30f;
#pragma unroll
            for (int nt = 0; nt < 8; nt++) {
                rmax0 = fmaxf(rmax0, fmaxf(sacc[nt][0], sacc[nt][1]));
                rmax1 = fmaxf(rmax1, fmaxf(sacc[nt][2], sacc[nt][3]));
            }
            rmax0 = fmaxf(rmax0, __shfl_xor_sync(0xffffffff, rmax0, 1));
            rmax0 = fmaxf(rmax0, __shfl_xor_sync(0xffffffff, rmax0, 2));
            rmax1 = fmaxf(rmax1, __shfl_xor_sync(0xffffffff, rmax1, 1));
            rmax1 = fmaxf(rmax1, __shfl_xor_sync(0xffffffff, rmax1, 2));

            const float mn0 = fmaxf(mrow[0], rmax0);
            const float mn1 = fmaxf(mrow[1], rmax1);
            const float corr0 = __expf(mrow[0] - mn0);
            const float corr1 = __expf(mrow[1] - mn1);
            mrow[0] = mn0; mrow[1] = mn1;

            float rs0 = 0.0f, rs1 = 0.0f;
            float* p0row = &Ps[(wrow + g) * APAD + 2 * tg];
            float* p1row = &Ps[(wrow + g + 8) * APAD + 2 * tg];
#pragma unroll
            for (int nt = 0; nt < 8; nt++) {
                const float e0 = __expf(sacc[nt][0] - mn0);
                const float e1 = __expf(sacc[nt][1] - mn0);
                const float e2 = __expf(sacc[nt][2] - mn1);
                const float e3 = __expf(sacc[nt][3] - mn1);
                rs0 += e0 + e1;
                rs1 += e2 + e3;
                *reinterpret_cast<float2*>(p0row + nt * 8) = make_float2(e0, e1);
                *reinterpret_cast<float2*>(p1row + nt * 8) = make_float2(e2, e3);
            }
            rs0 += __shfl_xor_sync(0xffffffff, rs0, 1);
            rs0 += __shfl_xor_sync(0xffffffff, rs0, 2);
            rs1 += __shfl_xor_sync(0xffffffff, rs1, 1);
            rs1 += __shfl_xor_sync(0xffffffff, rs1, 2);
            lrow[0] = lrow[0] * corr0 + rs0;
            lrow[1] = lrow[1] * corr1 + rs1;

#pragma unroll
            for (int nt = 0; nt < 8; nt++) {
                of[nt][0] *= corr0; of[nt][1] *= corr0;
                of[nt][2] *= corr1; of[nt][3] *= corr1;
            }
            __syncwarp();

            // ---- O += P * V ----
#pragma unroll
            for (int ks = 0; ks < 8; ks++) {
                const int kc = ks * 8 + tg;
                uint32_t a[4];
                a[0] = f2tf32(Ps[(wrow + g) * APAD + kc]);
                a[1] = f2tf32(Ps[(wrow + g + 8) * APAD + kc]);
                a[2] = f2tf32(Ps[(wrow + g) * APAD + kc + 4]);
                a[3] = f2tf32(Ps[(wrow + g + 8) * APAD + kc + 4]);
#pragma unroll
                for (int nt = 0; nt < 8; nt++) {
                    uint32_t bf[2];
                    bf[0] = f2tf32(vb[kc * APAD + nt * 8 + g]);
                    bf[1] = f2tf32(vb[(kc + 4) * APAD + nt * 8 + g]);
                    mma_tf32(of[nt], a, bf);
                }
            }
        }
        __syncthreads();
    }

    // ---- epilogue ----
    const float inv0 = 1.0f / lrow[0];
    const float inv1 = 1.0f / lrow[1];
    float* o0 = O + (((size_t)b * SEQ + r0g) * NHEAD + h) * HDIM;
    float* o1 = O + (((size_t)b * SEQ + r1g) * NHEAD + h) * HDIM;
#pragma unroll
    for (int nt = 0; nt < 8; nt++) {
        const int col = nt * 8 + 2 * tg;
        *reinterpret_cast<float2*>(o0 + col) = make_float2(of[nt][0] * inv0, of[nt][1] * inv0);
        *reinterpret_cast<float2*>(o1 + col) = make_float2(of[nt][2] * inv1, of[nt][3] * inv1);
    }
}

// ---------------------------------------------------------------------------
// kernel_launch
// ---------------------------------------------------------------------------
extern "C" void kernel_launch(void* const* d_in, const int* in_sizes, int n_in,
                              void* d_out, int out_size) {
    const float* x     = (const float*)d_in[0];
    const float* freqs = (const float*)d_in[1];
    const float* Wq    = (const float*)d_in[2];
    const float* Wk    = (const float*)d_in[3];
    const float* Wv    = (const float*)d_in[4];
    const float* Wo    = (const float*)d_in[5];
    float* out = (float*)d_out;

    float* q = nullptr; float* k = nullptr; float* v = nullptr; float* attn = nullptr;
    cudaGetSymbolAddress((void**)&q,    g_q);
    cudaGetSymbolAddress((void**)&k,    g_k);
    cudaGetSymbolAddress((void**)&v,    g_v);
    cudaGetSymbolAddress((void**)&attn, g_attn);

    const int gsmem = GSMEM_FLOATS * sizeof(float);   // 73728
    cudaFuncSetAttribute(gemm_tf32mma, cudaFuncAttributeMaxDynamicSharedMemorySize, gsmem);
    const int asmem = ASMEM_FLOATS * sizeof(float);   // 104448
    cudaFuncSetAttribute(flash_attn_mma, cudaFuncAttributeMaxDynamicSharedMemorySize, asmem);

    dim3 ggrid(CMODEL / BN, MROWS / BM);
    gemm_tf32mma<<<ggrid, 256, gsmem>>>(x, Wq, q, CMODEL, CMODEL);
    gemm_tf32mma<<<ggrid, 256, gsmem>>>(x, Wk, k, CMODEL, CMODEL);
    gemm_tf32mma<<<ggrid, 256, gsmem>>>(x, Wv, v, CMODEL, CMODEL);

    {
        long long total = (long long)BATCH * SEQ * NHEAD * (HDIM / 2);
        int threads = 256;
        int blocks = (int)((total + threads - 1) / threads);
        rope_kernel<<<blocks, threads>>>(q, k, freqs);
    }

    {
        dim3 agrid(SEQ / 128, NHEAD, BATCH);
        flash_attn_mma<<<agrid, 256, asmem>>>(q, k, v, attn);
    }

    gemm_tf32mma<<<ggrid, 256, gsmem>>>(attn, Wo, out, CMODEL, CMODEL);
}

// round 5
// speedup vs baseline: 3.4366x; 1.3389x over previous
#include <cuda_runtime.h>
#include <cuda_bf16.h>
#include <cstdint>
#include <math.h>

// Problem constants
#define BATCH 2
#define SEQ   2048
#define CMODEL 1024
#define NHEAD 16
#define HDIM  64
#define MROWS (BATCH * SEQ)   // 4096

// ---------------------------------------------------------------------------
// Scratch
// ---------------------------------------------------------------------------
__device__ float g_q[MROWS * CMODEL];
__device__ float g_k[MROWS * CMODEL];
__device__ float g_v[MROWS * CMODEL];
__device__ float g_attn[MROWS * CMODEL];

// ---------------------------------------------------------------------------
// Helpers
// ---------------------------------------------------------------------------
__device__ __forceinline__ uint32_t smem_u32(const void* p) {
    uint32_t a;
    asm("{ .reg .u64 t; cvta.to.shared.u64 t, %1; cvt.u32.u64 %0, t; }" : "=r"(a) : "l"(p));
    return a;
}
__device__ __forceinline__ void cp_async16(uint32_t s, const void* g) {
    asm volatile("cp.async.ca.shared.global [%0], [%1], 16;" :: "r"(s), "l"(g));
}
#define CP_COMMIT()  asm volatile("cp.async.commit_group;" ::: "memory")
#define CP_WAIT(N)   asm volatile("cp.async.wait_group %0;" :: "n"(N) : "memory")

__device__ __forceinline__ uint32_t f2tf32(float f) {
    uint32_t u;
    asm("cvt.rna.tf32.f32 %0, %1;" : "=r"(u) : "f"(f));
    return u;
}
__device__ __forceinline__ void mma_tf32(float (&d)[4], const uint32_t (&a)[4],
                                         const uint32_t (&b)[2]) {
    asm volatile(
        "mma.sync.aligned.m16n8k8.row.col.f32.tf32.tf32.f32 "
        "{%0,%1,%2,%3}, {%4,%5,%6,%7}, {%8,%9}, {%0,%1,%2,%3};"
        : "+f"(d[0]), "+f"(d[1]), "+f"(d[2]), "+f"(d[3])
        : "r"(a[0]), "r"(a[1]), "r"(a[2]), "r"(a[3]), "r"(b[0]), "r"(b[1]));
}

// ---------------------------------------------------------------------------
// TF32 mma.sync GEMM body: C[m][n] = sum_k A[m][k] * W[n][k]
// CTA tile 256x128, BK=32, 256 threads = 8 warps in 4(M) x 2(N);
// warp tile 64x64 (4x8 mma tiles). Optional fused RoPE on epilogue.
// ---------------------------------------------------------------------------
#define BK 32
#define KST 36                       // padded row stride (floats)
#define ATF (256 * KST)              // A tile floats
#define WTF (128 * KST)              // W tile floats
#define STAGEF (ATF + WTF)
#define G2SMEM_FLOATS (2 * STAGEF)   // 110592 bytes

__device__ __forceinline__ void gemm_body(const float* __restrict__ A,
                                          const float* __restrict__ W,
                                          float* __restrict__ C,
                                          const float* __restrict__ freqs,
                                          int m0, int n0, bool rope,
                                          float* smem) {
    const int K = CMODEL, N = CMODEL;
    float* As[2] = { smem,          smem + STAGEF };
    float* Ws[2] = { smem + ATF,    smem + STAGEF + ATF };

    const int tid  = threadIdx.x;
    const int lane = tid & 31;
    const int wid  = tid >> 5;
    const int g    = lane >> 2;
    const int tg   = lane & 3;
    const int wm   = (wid & 3) * 64;
    const int wn   = (wid >> 2) * 64;

    // loaders: A tile 2048 float4 (8/thread), W tile 1024 float4 (4/thread)
    const int arow = tid >> 1;             // base pattern: f=tid+256i -> row=f>>3
    // use f-based mapping directly in the loop below.

    float acc[4][8][4];
#pragma unroll
    for (int mt = 0; mt < 4; mt++)
#pragma unroll
        for (int nt = 0; nt < 8; nt++)
#pragma unroll
            for (int r = 0; r < 4; r++) acc[mt][nt][r] = 0.0f;

    const int ntiles = K / BK;
    (void)arow;

    auto load_tile = [&](int kt, int stg) {
        const int ko = kt * BK;
#pragma unroll
        for (int i = 0; i < 8; i++) {
            const int f = tid + 256 * i;       // 0..2047
            const int row = f >> 3;
            const int c4 = (f & 7) * 4;
            cp_async16(smem_u32(&As[stg][row * KST + c4]),
                       &A[(size_t)(m0 + row) * K + ko + c4]);
        }
#pragma unroll
        for (int i = 0; i < 4; i++) {
            const int f = tid + 256 * i;       // 0..1023
            const int row = f >> 3;
            const int c4 = (f & 7) * 4;
            cp_async16(smem_u32(&Ws[stg][row * KST + c4]),
                       &W[(size_t)(n0 + row) * K + ko + c4]);
        }
    };

    load_tile(0, 0);
    CP_COMMIT();

    for (int kt = 0; kt < ntiles; kt++) {
        const int buf = kt & 1;
        if (kt + 1 < ntiles) {
            load_tile(kt + 1, (kt + 1) & 1);
            CP_COMMIT();
            CP_WAIT(1);
        } else {
            CP_WAIT(0);
        }
        __syncthreads();

        const float* at = As[buf];
        const float* wt = Ws[buf];
#pragma unroll
        for (int ks = 0; ks < 4; ks++) {
            const int kc = ks * 8 + tg;
            uint32_t a[4][4];
#pragma unroll
            for (int mt = 0; mt < 4; mt++) {
                const int r0 = (wm + mt * 16 + g) * KST;
                a[mt][0] = f2tf32(at[r0 + kc]);
                a[mt][1] = f2tf32(at[r0 + 8 * KST + kc]);
                a[mt][2] = f2tf32(at[r0 + kc + 4]);
                a[mt][3] = f2tf32(at[r0 + 8 * KST + kc + 4]);
            }
            uint32_t b[8][2];
#pragma unroll
            for (int nt = 0; nt < 8; nt++) {
                const int r0 = (wn + nt * 8 + g) * KST;
                b[nt][0] = f2tf32(wt[r0 + kc]);
                b[nt][1] = f2tf32(wt[r0 + kc + 4]);
            }
#pragma unroll
            for (int mt = 0; mt < 4; mt++)
#pragma unroll
                for (int nt = 0; nt < 8; nt++)
                    mma_tf32(acc[mt][nt], a[mt], b[nt]);
        }
        __syncthreads();
    }

    // epilogue (optionally fused RoPE; accum pair (c0,c1) = cols (2i, 2i+1))
#pragma unroll
    for (int mt = 0; mt < 4; mt++) {
        const int row = m0 + wm + mt * 16 + g;
        const int t0 = row & (SEQ - 1);
        const int t1 = (row + 8) & (SEQ - 1);
#pragma unroll
        for (int nt = 0; nt < 8; nt++) {
            const int col = n0 + wn + nt * 8 + 2 * tg;
            float2 v0 = make_float2(acc[mt][nt][0], acc[mt][nt][1]);
            float2 v1 = make_float2(acc[mt][nt][2], acc[mt][nt][3]);
            if (rope) {
                const int fo = (col & 62);
                float c0 = freqs[t0 * HDIM + fo], s0 = freqs[t0 * HDIM + fo + 1];
                float c1 = freqs[t1 * HDIM + fo], s1 = freqs[t1 * HDIM + fo + 1];
                v0 = make_float2(v0.x * c0 - v0.y * s0, v0.x * s0 + v0.y * c0);
                v1 = make_float2(v1.x * c1 - v1.y * s1, v1.x * s1 + v1.y * c1);
            }
            *reinterpret_cast<float2*>(&C[(size_t)row * N + col]) = v0;
            *reinterpret_cast<float2*>(&C[(size_t)(row + 8) * N + col]) = v1;
        }
    }
}

// Fused QKV + RoPE: grid.x in 0..23 -> (matrix, n-block); grid.y -> m-block
__global__ __launch_bounds__(256, 1) void gemm_qkv(const float* __restrict__ x,
                                                   const float* __restrict__ Wq,
                                                   const float* __restrict__ Wk,
                                                   const float* __restrict__ Wv,
                                                   float* __restrict__ q,
                                                   float* __restrict__ k,
                                                   float* __restrict__ v,
                                                   const float* __restrict__ freqs) {
    extern __shared__ float smem[];
    const int wsel = blockIdx.x >> 3;
    const int n0 = (blockIdx.x & 7) * 128;
    const int m0 = blockIdx.y * 256;
    const float* W = (wsel == 0) ? Wq : (wsel == 1) ? Wk : Wv;
    float* C = (wsel == 0) ? q : (wsel == 1) ? k : v;
    gemm_body(x, W, C, freqs, m0, n0, wsel < 2, smem);
}

__global__ __launch_bounds__(256, 1) void gemm_proj(const float* __restrict__ A,
                                                    const float* __restrict__ W,
                                                    float* __restrict__ C) {
    extern __shared__ float smem[];
    gemm_body(A, W, C, nullptr, blockIdx.y * 256, blockIdx.x * 128, false, smem);
}

// ---------------------------------------------------------------------------
// Tensor-core flash-attention (unchanged from passing R4)
// ---------------------------------------------------------------------------
#define APAD 68
#define ATILE (64 * APAD)
#define ASMEM_FLOATS (4 * ATILE + 128 * APAD)

__global__ __launch_bounds__(256, 1) void flash_attn_mma(const float* __restrict__ Q,
                                                         const float* __restrict__ K,
                                                         const float* __restrict__ V,
                                                         float* __restrict__ O) {
    extern __shared__ float sm[];
    float* Ksm[2] = { sm,             sm + 2 * ATILE };
    float* Vsm[2] = { sm + ATILE,     sm + 3 * ATILE };
    float* Ps = sm + 4 * ATILE;

    const int tid  = threadIdx.x;
    const int lane = tid & 31;
    const int wid  = tid >> 5;
    const int g    = lane >> 2;
    const int tg   = lane & 3;

    const int qb = (int)gridDim.x - 1 - (int)blockIdx.x;
    const int h  = blockIdx.y;
    const int b  = blockIdx.z;
    const int q0 = qb * 128;
    const int wrow = wid * 16;
    const int r0g = q0 + wrow + g;
    const int r1g = r0g + 8;

    const float scale = 0.125f;
    uint32_t qf[8][4];
    {
        const float* q0p = Q + (((size_t)b * SEQ + r0g) * NHEAD + h) * HDIM;
        const float* q1p = Q + (((size_t)b * SEQ + r1g) * NHEAD + h) * HDIM;
#pragma unroll
        for (int ks = 0; ks < 8; ks++) {
            const int kc = ks * 8 + tg;
            qf[ks][0] = f2tf32(q0p[kc] * scale);
            qf[ks][1] = f2tf32(q1p[kc] * scale);
            qf[ks][2] = f2tf32(q0p[kc + 4] * scale);
            qf[ks][3] = f2tf32(q1p[kc + 4] * scale);
        }
    }

    float of[8][4];
#pragma unroll
    for (int nt = 0; nt < 8; nt++)
#pragma unroll
        for (int r = 0; r < 4; r++) of[nt][r] = 0.0f;
    float mrow[2] = { -1e30f, -1e30f };
    float lrow[2] = { 0.0f, 0.0f };

    const int ntiles = (q0 + 128) / 64;

    const uint32_t ks0 = smem_u32(Ksm[0]);
    const uint32_t vs0 = smem_u32(Vsm[0]);
    const uint32_t stageB = 2 * ATILE * 4;

    auto prefetch = [&](int t, int s) {
        const int kt = t * 64;
#pragma unroll
        for (int i = 0; i < 4; i++) {
            const int f = tid + 256 * i;
            const int row = f >> 4;
            const int c4 = (f & 15) * 4;
            const size_t gsrc = (((size_t)b * SEQ + kt + row) * NHEAD + h) * HDIM + c4;
            const uint32_t soff = s * stageB + (row * APAD + c4) * 4;
            cp_async16(ks0 + soff, &K[gsrc]);
            cp_async16(vs0 + soff, &V[gsrc]);
        }
    };

    prefetch(0, 0);
    CP_COMMIT();

    for (int t = 0; t < ntiles; t++) {
        const int kt = t * 64;
        if (t + 1 < ntiles) {
            prefetch(t + 1, (t + 1) & 1);
            CP_COMMIT();
            CP_WAIT(1);
        } else {
            CP_WAIT(0);
        }
        __syncthreads();

        const bool skip = kt > q0 + wrow + 15;
        if (!skip) {
            const float* kb = Ksm[t & 1];
            const float* vb = Vsm[t & 1];

            float sacc[8][4];
#pragma unroll
            for (int nt = 0; nt < 8; nt++)
#pragma unroll
                for (int r = 0; r < 4; r++) sacc[nt][r] = 0.0f;

#pragma unroll
            for (int ks = 0; ks < 8; ks++) {
                const int kc = ks * 8 + tg;
#pragma unroll
                for (int nt = 0; nt < 8; nt++) {
                    uint32_t bf[2];
                    bf[0] = f2tf32(kb[(nt * 8 + g) * APAD + kc]);
                    bf[1] = f2tf32(kb[(nt * 8 + g) * APAD + kc + 4]);
                    mma_tf32(sacc[nt], qf[ks], bf);
                }
            }

            if (kt + 63 > q0 + wrow) {
#pragma unroll
                for (int nt = 0; nt < 8; nt++) {
                    const int c = kt + nt * 8 + 2 * tg;
                    if (c > r0g)     sacc[nt][0] = -1e30f;
                    if (c + 1 > r0g) sacc[nt][1] = -1e30f;
                    if (c > r1g)     sacc[nt][2] = -1e30f;
                    if (c + 1 > r1g) sacc[nt][3] = -1e30f;
                }
            }

            float rmax0 = -1e30f, rmax1 = -1e30f;
#pragma unroll
            for (int nt = 0; nt < 8; nt++) {
                rmax0 = fmaxf(rmax0, fmaxf(sacc[nt][0], sacc[nt][1]));
                rmax1 = fmaxf(rmax1, fmaxf(sacc[nt][2], sacc[nt][3]));
            }
            rmax0 = fmaxf(rmax0, __shfl_xor_sync(0xffffffff, rmax0, 1));
            rmax0 = fmaxf(rmax0, __shfl_xor_sync(0xffffffff, rmax0, 2));
            rmax1 = fmaxf(rmax1, __shfl_xor_sync(0xffffffff, rmax1, 1));
            rmax1 = fmaxf(rmax1, __shfl_xor_sync(0xffffffff, rmax1, 2));

            const float mn0 = fmaxf(mrow[0], rmax0);
            const float mn1 = fmaxf(mrow[1], rmax1);
            const float corr0 = __expf(mrow[0] - mn0);
            const float corr1 = __expf(mrow[1] - mn1);
            mrow[0] = mn0; mrow[1] = mn1;

            float rs0 = 0.0f, rs1 = 0.0f;
            float* p0row = &Ps[(wrow + g) * APAD + 2 * tg];
            float* p1row = &Ps[(wrow + g + 8) * APAD + 2 * tg];
#pragma unroll
            for (int nt = 0; nt < 8; nt++) {
                const float e0 = __expf(sacc[nt][0] - mn0);
                const float e1 = __expf(sacc[nt][1] - mn0);
                const float e2 = __expf(sacc[nt][2] - mn1);
                const float e3 = __expf(sacc[nt][3] - mn1);
                rs0 += e0 + e1;
                rs1 += e2 + e3;
                *reinterpret_cast<float2*>(p0row + nt * 8) = make_float2(e0, e1);
                *reinterpret_cast<float2*>(p1row + nt * 8) = make_float2(e2, e3);
            }
            rs0 += __shfl_xor_sync(0xffffffff, rs0, 1);
            rs0 += __shfl_xor_sync(0xffffffff, rs0, 2);
            rs1 += __shfl_xor_sync(0xffffffff, rs1, 1);
            rs1 += __shfl_xor_sync(0xffffffff, rs1, 2);
            lrow[0] = lrow[0] * corr0 + rs0;
            lrow[1] = lrow[1] * corr1 + rs1;

#pragma unroll
            for (int nt = 0; nt < 8; nt++) {
                of[nt][0] *= corr0; of[nt][1] *= corr0;
                of[nt][2] *= corr1; of[nt][3] *= corr1;
            }
            __syncwarp();

#pragma unroll
            for (int ks = 0; ks < 8; ks++) {
                const int kc = ks * 8 + tg;
                uint32_t a[4];
                a[0] = f2tf32(Ps[(wrow + g) * APAD + kc]);
                a[1] = f2tf32(Ps[(wrow + g + 8) * APAD + kc]);
                a[2] = f2tf32(Ps[(wrow + g) * APAD + kc + 4]);
                a[3] = f2tf32(Ps[(wrow + g + 8) * APAD + kc + 4]);
#pragma unroll
                for (int nt = 0; nt < 8; nt++) {
                    uint32_t bf[2];
                    bf[0] = f2tf32(vb[kc * APAD + nt * 8 + g]);
                    bf[1] = f2tf32(vb[(kc + 4) * APAD + nt * 8 + g]);
                    mma_tf32(of[nt], a, bf);
                }
            }
        }
        __syncthreads();
    }

    const float inv0 = 1.0f / lrow[0];
    const float inv1 = 1.0f / lrow[1];
    float* o0 = O + (((size_t)b * SEQ + r0g) * NHEAD + h) * HDIM;
    float* o1 = O + (((size_t)b * SEQ + r1g) * NHEAD + h) * HDIM;
#pragma unroll
    for (int nt = 0; nt < 8; nt++) {
        const int col = nt * 8 + 2 * tg;
        *reinterpret_cast<float2*>(o0 + col) = make_float2(of[nt][0] * inv0, of[nt][1] * inv0);
        *reinterpret_cast<float2*>(o1 + col) = make_float2(of[nt][2] * inv1, of[nt][3] * inv1);
    }
}

// ---------------------------------------------------------------------------
// kernel_launch
// ---------------------------------------------------------------------------
extern "C" void kernel_launch(void* const* d_in, const int* in_sizes, int n_in,
                              void* d_out, int out_size) {
    const float* x     = (const float*)d_in[0];
    const float* freqs = (const float*)d_in[1];
    const float* Wq    = (const float*)d_in[2];
    const float* Wk    = (const float*)d_in[3];
    const float* Wv    = (const float*)d_in[4];
    const float* Wo    = (const float*)d_in[5];
    float* out = (float*)d_out;

    float* q = nullptr; float* k = nullptr; float* v = nullptr; float* attn = nullptr;
    cudaGetSymbolAddress((void**)&q,    g_q);
    cudaGetSymbolAddress((void**)&k,    g_k);
    cudaGetSymbolAddress((void**)&v,    g_v);
    cudaGetSymbolAddress((void**)&attn, g_attn);

    const int gsmem = G2SMEM_FLOATS * sizeof(float);   // 110592
    cudaFuncSetAttribute(gemm_qkv,  cudaFuncAttributeMaxDynamicSharedMemorySize, gsmem);
    cudaFuncSetAttribute(gemm_proj, cudaFuncAttributeMaxDynamicSharedMemorySize, gsmem);
    const int asmem = ASMEM_FLOATS * sizeof(float);    // 104448
    cudaFuncSetAttribute(flash_attn_mma, cudaFuncAttributeMaxDynamicSharedMemorySize, asmem);

    gemm_qkv<<<dim3(24, MROWS / 256), 256, gsmem>>>(x, Wq, Wk, Wv, q, k, v, freqs);

    {
        dim3 agrid(SEQ / 128, NHEAD, BATCH);
        flash_attn_mma<<<agrid, 256, asmem>>>(q, k, v, attn);
    }

    gemm_proj<<<dim3(CMODEL / 128, MROWS / 256), 256, gsmem>>>(attn, Wo, out);
}

// round 6
// speedup vs baseline: 3.4470x; 1.0030x over previous
#include <cuda_runtime.h>
#include <cuda_bf16.h>
#include <cstdint>
#include <math.h>

// Problem constants
#define BATCH 2
#define SEQ   2048
#define CMODEL 1024
#define NHEAD 16
#define HDIM  64
#define MROWS (BATCH * SEQ)   // 4096

// ---------------------------------------------------------------------------
// Scratch
// ---------------------------------------------------------------------------
__device__ float g_q[MROWS * CMODEL];
__device__ float g_k[MROWS * CMODEL];
__device__ float g_v[MROWS * CMODEL];
__device__ float g_attn[MROWS * CMODEL];

// ---------------------------------------------------------------------------
// Helpers
// ---------------------------------------------------------------------------
__device__ __forceinline__ uint32_t smem_u32(const void* p) {
    uint32_t a;
    asm("{ .reg .u64 t; cvta.to.shared.u64 t, %1; cvt.u32.u64 %0, t; }" : "=r"(a) : "l"(p));
    return a;
}
__device__ __forceinline__ void cp_async16(uint32_t s, const void* g) {
    asm volatile("cp.async.ca.shared.global [%0], [%1], 16;" :: "r"(s), "l"(g));
}
#define CP_COMMIT()  asm volatile("cp.async.commit_group;" ::: "memory")
#define CP_WAIT(N)   asm volatile("cp.async.wait_group %0;" :: "n"(N) : "memory")

__device__ __forceinline__ uint32_t f2tf32(float f) {
    uint32_t u;
    asm("cvt.rna.tf32.f32 %0, %1;" : "=r"(u) : "f"(f));
    return u;
}
__device__ __forceinline__ void mma_tf32(float (&d)[4], const uint32_t (&a)[4],
                                         const uint32_t (&b)[2]) {
    asm volatile(
        "mma.sync.aligned.m16n8k8.row.col.f32.tf32.tf32.f32 "
        "{%0,%1,%2,%3}, {%4,%5,%6,%7}, {%8,%9}, {%0,%1,%2,%3};"
        : "+f"(d[0]), "+f"(d[1]), "+f"(d[2]), "+f"(d[3])
        : "r"(a[0]), "r"(a[1]), "r"(a[2]), "r"(a[3]), "r"(b[0]), "r"(b[1]));
}

// ---------------------------------------------------------------------------
// TF32 mma.sync GEMM body: C[m][n] = sum_k A[m][k] * W[n][k]
// CTA tile 256x128, BK=32, 512 threads = 16 warps in 4(M) x 4(N);
// warp tile 64x32 (4x4 mma tiles, 64 accum regs). Optional fused RoPE.
// ---------------------------------------------------------------------------
#define BK 32
#define KST 36                       // padded row stride (floats)
#define ATF (256 * KST)              // A tile floats
#define WTF (128 * KST)              // W tile floats
#define STAGEF (ATF + WTF)
#define G2SMEM_FLOATS (2 * STAGEF)   // 110592 bytes

__device__ __forceinline__ void gemm_body(const float* __restrict__ A,
                                          const float* __restrict__ W,
                                          float* __restrict__ C,
                                          const float* __restrict__ freqs,
                                          int m0, int n0, bool rope,
                                          float* smem) {
    const int K = CMODEL, N = CMODEL;
    float* As[2] = { smem,          smem + STAGEF };
    float* Ws[2] = { smem + ATF,    smem + STAGEF + ATF };

    const int tid  = threadIdx.x;
    const int lane = tid & 31;
    const int wid  = tid >> 5;       // 0..15
    const int g    = lane >> 2;
    const int tg   = lane & 3;
    const int wm   = (wid & 3) * 64;     // 4 M-groups
    const int wn   = (wid >> 2) * 32;    // 4 N-groups

    float acc[4][4][4];
#pragma unroll
    for (int mt = 0; mt < 4; mt++)
#pragma unroll
        for (int nt = 0; nt < 4; nt++)
#pragma unroll
            for (int r = 0; r < 4; r++) acc[mt][nt][r] = 0.0f;

    const int ntiles = K / BK;

    // loaders (512 threads): A tile 2048 float4 -> 4/thread; W tile 1024 -> 2/thread
    auto load_tile = [&](int kt, int stg) {
        const int ko = kt * BK;
#pragma unroll
        for (int i = 0; i < 4; i++) {
            const int f = tid + 512 * i;       // 0..2047
            const int row = f >> 3;
            const int c4 = (f & 7) * 4;
            cp_async16(smem_u32(&As[stg][row * KST + c4]),
                       &A[(size_t)(m0 + row) * K + ko + c4]);
        }
#pragma unroll
        for (int i = 0; i < 2; i++) {
            const int f = tid + 512 * i;       // 0..1023
            const int row = f >> 3;
            const int c4 = (f & 7) * 4;
            cp_async16(smem_u32(&Ws[stg][row * KST + c4]),
                       &W[(size_t)(n0 + row) * K + ko + c4]);
        }
    };

    load_tile(0, 0);
    CP_COMMIT();

    for (int kt = 0; kt < ntiles; kt++) {
        const int buf = kt & 1;
        if (kt + 1 < ntiles) {
            load_tile(kt + 1, (kt + 1) & 1);
            CP_COMMIT();
            CP_WAIT(1);
        } else {
            CP_WAIT(0);
        }
        __syncthreads();

        const float* at = As[buf];
        const float* wt = Ws[buf];
#pragma unroll
        for (int ks = 0; ks < 4; ks++) {
            const int kc = ks * 8 + tg;
            uint32_t a[4][4];
#pragma unroll
            for (int mt = 0; mt < 4; mt++) {
                const int r0 = (wm + mt * 16 + g) * KST;
                a[mt][0] = f2tf32(at[r0 + kc]);
                a[mt][1] = f2tf32(at[r0 + 8 * KST + kc]);
                a[mt][2] = f2tf32(at[r0 + kc + 4]);
                a[mt][3] = f2tf32(at[r0 + 8 * KST + kc + 4]);
            }
            uint32_t b[4][2];
#pragma unroll
            for (int nt = 0; nt < 4; nt++) {
                const int r0 = (wn + nt * 8 + g) * KST;
                b[nt][0] = f2tf32(wt[r0 + kc]);
                b[nt][1] = f2tf32(wt[r0 + kc + 4]);
            }
#pragma unroll
            for (int mt = 0; mt < 4; mt++)
#pragma unroll
                for (int nt = 0; nt < 4; nt++)
                    mma_tf32(acc[mt][nt], a[mt], b[nt]);
        }
        __syncthreads();
    }

    // epilogue (optionally fused RoPE; accum pair (c0,c1) = cols (2i, 2i+1))
#pragma unroll
    for (int mt = 0; mt < 4; mt++) {
        const int row = m0 + wm + mt * 16 + g;
        const int t0 = row & (SEQ - 1);
        const int t1 = (row + 8) & (SEQ - 1);
#pragma unroll
        for (int nt = 0; nt < 4; nt++) {
            const int col = n0 + wn + nt * 8 + 2 * tg;
            float2 v0 = make_float2(acc[mt][nt][0], acc[mt][nt][1]);
            float2 v1 = make_float2(acc[mt][nt][2], acc[mt][nt][3]);
            if (rope) {
                const int fo = (col & 62);
                float c0 = freqs[t0 * HDIM + fo], s0 = freqs[t0 * HDIM + fo + 1];
                float c1 = freqs[t1 * HDIM + fo], s1 = freqs[t1 * HDIM + fo + 1];
                v0 = make_float2(v0.x * c0 - v0.y * s0, v0.x * s0 + v0.y * c0);
                v1 = make_float2(v1.x * c1 - v1.y * s1, v1.x * s1 + v1.y * c1);
            }
            *reinterpret_cast<float2*>(&C[(size_t)row * N + col]) = v0;
            *reinterpret_cast<float2*>(&C[(size_t)(row + 8) * N + col]) = v1;
        }
    }
}

// Fused QKV + RoPE: grid.x in 0..23 -> (matrix, n-block); grid.y -> m-block
__global__ __launch_bounds__(512, 1) void gemm_qkv(const float* __restrict__ x,
                                                   const float* __restrict__ Wq,
                                                   const float* __restrict__ Wk,
                                                   const float* __restrict__ Wv,
                                                   float* __restrict__ q,
                                                   float* __restrict__ k,
                                                   float* __restrict__ v,
                                                   const float* __restrict__ freqs) {
    extern __shared__ float smem[];
    const int wsel = blockIdx.x >> 3;
    const int n0 = (blockIdx.x & 7) * 128;
    const int m0 = blockIdx.y * 256;
    const float* W = (wsel == 0) ? Wq : (wsel == 1) ? Wk : Wv;
    float* C = (wsel == 0) ? q : (wsel == 1) ? k : v;
    gemm_body(x, W, C, freqs, m0, n0, wsel < 2, smem);
}

__global__ __launch_bounds__(512, 1) void gemm_proj(const float* __restrict__ A,
                                                    const float* __restrict__ W,
                                                    float* __restrict__ C) {
    extern __shared__ float smem[];
    gemm_body(A, W, C, nullptr, blockIdx.y * 256, blockIdx.x * 128, false, smem);
}

// ---------------------------------------------------------------------------
// Tensor-core flash-attention (unchanged from passing R4/R5)
// ---------------------------------------------------------------------------
#define APAD 68
#define ATILE (64 * APAD)
#define ASMEM_FLOATS (4 * ATILE + 128 * APAD)

__global__ __launch_bounds__(256, 1) void flash_attn_mma(const float* __restrict__ Q,
                                                         const float* __restrict__ K,
                                                         const float* __restrict__ V,
                                                         float* __restrict__ O) {
    extern __shared__ float sm[];
    float* Ksm[2] = { sm,             sm + 2 * ATILE };
    float* Vsm[2] = { sm + ATILE,     sm + 3 * ATILE };
    float* Ps = sm + 4 * ATILE;

    const int tid  = threadIdx.x;
    const int lane = tid & 31;
    const int wid  = tid >> 5;
    const int g    = lane >> 2;
    const int tg   = lane & 3;

    const int qb = (int)gridDim.x - 1 - (int)blockIdx.x;
    const int h  = blockIdx.y;
    const int b  = blockIdx.z;
    const int q0 = qb * 128;
    const int wrow = wid * 16;
    const int r0g = q0 + wrow + g;
    const int r1g = r0g + 8;

    const float scale = 0.125f;
    uint32_t qf[8][4];
    {
        const float* q0p = Q + (((size_t)b * SEQ + r0g) * NHEAD + h) * HDIM;
        const float* q1p = Q + (((size_t)b * SEQ + r1g) * NHEAD + h) * HDIM;
#pragma unroll
        for (int ks = 0; ks < 8; ks++) {
            const int kc = ks * 8 + tg;
            qf[ks][0] = f2tf32(q0p[kc] * scale);
            qf[ks][1] = f2tf32(q1p[kc] * scale);
            qf[ks][2] = f2tf32(q0p[kc + 4] * scale);
            qf[ks][3] = f2tf32(q1p[kc + 4] * scale);
        }
    }

    float of[8][4];
#pragma unroll
    for (int nt = 0; nt < 8; nt++)
#pragma unroll
        for (int r = 0; r < 4; r++) of[nt][r] = 0.0f;
    float mrow[2] = { -1e30f, -1e30f };
    float lrow[2] = { 0.0f, 0.0f };

    const int ntiles = (q0 + 128) / 64;

    const uint32_t ks0 = smem_u32(Ksm[0]);
    const uint32_t vs0 = smem_u32(Vsm[0]);
    const uint32_t stageB = 2 * ATILE * 4;

    auto prefetch = [&](int t, int s) {
        const int kt = t * 64;
#pragma unroll
        for (int i = 0; i < 4; i++) {
            const int f = tid + 256 * i;
            const int row = f >> 4;
            const int c4 = (f & 15) * 4;
            const size_t gsrc = (((size_t)b * SEQ + kt + row) * NHEAD + h) * HDIM + c4;
            const uint32_t soff = s * stageB + (row * APAD + c4) * 4;
            cp_async16(ks0 + soff, &K[gsrc]);
            cp_async16(vs0 + soff, &V[gsrc]);
        }
    };

    prefetch(0, 0);
    CP_COMMIT();

    for (int t = 0; t < ntiles; t++) {
        const int kt = t * 64;
        if (t + 1 < ntiles) {
            prefetch(t + 1, (t + 1) & 1);
            CP_COMMIT();
            CP_WAIT(1);
        } else {
            CP_WAIT(0);
        }
        __syncthreads();

        const bool skip = kt > q0 + wrow + 15;
        if (!skip) {
            const float* kb = Ksm[t & 1];
            const float* vb = Vsm[t & 1];

            float sacc[8][4];
#pragma unroll
            for (int nt = 0; nt < 8; nt++)
#pragma unroll
                for (int r = 0; r < 4; r++) sacc[nt][r] = 0.0f;

#pragma unroll
            for (int ks = 0; ks < 8; ks++) {
                const int kc = ks * 8 + tg;
#pragma unroll
                for (int nt = 0; nt < 8; nt++) {
                    uint32_t bf[2];
                    bf[0] = f2tf32(kb[(nt * 8 + g) * APAD + kc]);
                    bf[1] = f2tf32(kb[(nt * 8 + g) * APAD + kc + 4]);
                    mma_tf32(sacc[nt], qf[ks], bf);
                }
            }

            if (kt + 63 > q0 + wrow) {
#pragma unroll
                for (int nt = 0; nt < 8; nt++) {
                    const int c = kt + nt * 8 + 2 * tg;
                    if (c > r0g)     sacc[nt][0] = -1e30f;
                    if (c + 1 > r0g) sacc[nt][1] = -1e30f;
                    if (c > r1g)     sacc[nt][2] = -1e30f;
                    if (c + 1 > r1g) sacc[nt][3] = -1e30f;
                }
            }

            float rmax0 = -1e30f, rmax1 = -1e30f;
#pragma unroll
            for (int nt = 0; nt < 8; nt++) {
                rmax0 = fmaxf(rmax0, fmaxf(sacc[nt][0], sacc[nt][1]));
                rmax1 = fmaxf(rmax1, fmaxf(sacc[nt][2], sacc[nt][3]));
            }
            rmax0 = fmaxf(rmax0, __shfl_xor_sync(0xffffffff, rmax0, 1));
            rmax0 = fmaxf(rmax0, __shfl_xor_sync(0xffffffff, rmax0, 2));
            rmax1 = fmaxf(rmax1, __shfl_xor_sync(0xffffffff, rmax1, 1));
            rmax1 = fmaxf(rmax1, __shfl_xor_sync(0xffffffff, rmax1, 2));

            const float mn0 = fmaxf(mrow[0], rmax0);
            const float mn1 = fmaxf(mrow[1], rmax1);
            const float corr0 = __expf(mrow[0] - mn0);
            const float corr1 = __expf(mrow[1] - mn1);
            mrow[0] = mn0; mrow[1] = mn1;

            float rs0 = 0.0f, rs1 = 0.0f;
            float* p0row = &Ps[(wrow + g) * APAD + 2 * tg];
            float* p1row = &Ps[(wrow + g + 8) * APAD + 2 * tg];
#pragma unroll
            for (int nt = 0; nt < 8; nt++) {
                const float e0 = __expf(sacc[nt][0] - mn0);
                const float e1 = __expf(sacc[nt][1] - mn0);
                const float e2 = __expf(sacc[nt][2] - mn1);
                const float e3 = __expf(sacc[nt][3] - mn1);
                rs0 += e0 + e1;
                rs1 += e2 + e3;
                *reinterpret_cast<float2*>(p0row + nt * 8) = make_float2(e0, e1);
                *reinterpret_cast<float2*>(p1row + nt * 8) = make_float2(e2, e3);
            }
            rs0 += __shfl_xor_sync(0xffffffff, rs0, 1);
            rs0 += __shfl_xor_sync(0xffffffff, rs0, 2);
            rs1 += __shfl_xor_sync(0xffffffff, rs1, 1);
            rs1 += __shfl_xor_sync(0xffffffff, rs1, 2);
            lrow[0] = lrow[0] * corr0 + rs0;
            lrow[1] = lrow[1] * corr1 + rs1;

#pragma unroll
            for (int nt = 0; nt < 8; nt++) {
                of[nt][0] *= corr0; of[nt][1] *= corr0;
                of[nt][2] *= corr1; of[nt][3] *= corr1;
            }
            __syncwarp();

#pragma unroll
            for (int ks = 0; ks < 8; ks++) {
                const int kc = ks * 8 + tg;
                uint32_t a[4];
                a[0] = f2tf32(Ps[(wrow + g) * APAD + kc]);
                a[1] = f2tf32(Ps[(wrow + g + 8) * APAD + kc]);
                a[2] = f2tf32(Ps[(wrow + g) * APAD + kc + 4]);
                a[3] = f2tf32(Ps[(wrow + g + 8) * APAD + kc + 4]);
#pragma unroll
                for (int nt = 0; nt < 8; nt++) {
                    uint32_t bf[2];
                    bf[0] = f2tf32(vb[kc * APAD + nt * 8 + g]);
                    bf[1] = f2tf32(vb[(kc + 4) * APAD + nt * 8 + g]);
                    mma_tf32(of[nt], a, bf);
                }
            }
        }
        __syncthreads();
    }

    const float inv0 = 1.0f / lrow[0];
    const float inv1 = 1.0f / lrow[1];
    float* o0 = O + (((size_t)b * SEQ + r0g) * NHEAD + h) * HDIM;
    float* o1 = O + (((size_t)b * SEQ + r1g) * NHEAD + h) * HDIM;
#pragma unroll
    for (int nt = 0; nt < 8; nt++) {
        const int col = nt * 8 + 2 * tg;
        *reinterpret_cast<float2*>(o0 + col) = make_float2(of[nt][0] * inv0, of[nt][1] * inv0);
        *reinterpret_cast<float2*>(o1 + col) = make_float2(of[nt][2] * inv1, of[nt][3] * inv1);
    }
}

// ---------------------------------------------------------------------------
// kernel_launch
// ---------------------------------------------------------------------------
extern "C" void kernel_launch(void* const* d_in, const int* in_sizes, int n_in,
                              void* d_out, int out_size) {
    const float* x     = (const float*)d_in[0];
    const float* freqs = (const float*)d_in[1];
    const float* Wq    = (const float*)d_in[2];
    const float* Wk    = (const float*)d_in[3];
    const float* Wv    = (const float*)d_in[4];
    const float* Wo    = (const float*)d_in[5];
    float* out = (float*)d_out;

    float* q = nullptr; float* k = nullptr; float* v = nullptr; float* attn = nullptr;
    cudaGetSymbolAddress((void**)&q,    g_q);
    cudaGetSymbolAddress((void**)&k,    g_k);
    cudaGetSymbolAddress((void**)&v,    g_v);
    cudaGetSymbolAddress((void**)&attn, g_attn);

    const int gsmem = G2SMEM_FLOATS * sizeof(float);   // 110592
    cudaFuncSetAttribute(gemm_qkv,  cudaFuncAttributeMaxDynamicSharedMemorySize, gsmem);
    cudaFuncSetAttribute(gemm_proj, cudaFuncAttributeMaxDynamicSharedMemorySize, gsmem);
    const int asmem = ASMEM_FLOATS * sizeof(float);    // 104448
    cudaFuncSetAttribute(flash_attn_mma, cudaFuncAttributeMaxDynamicSharedMemorySize, asmem);

    gemm_qkv<<<dim3(24, MROWS / 256), 512, gsmem>>>(x, Wq, Wk, Wv, q, k, v, freqs);

    {
        dim3 agrid(SEQ / 128, NHEAD, BATCH);
        flash_attn_mma<<<agrid, 256, asmem>>>(q, k, v, attn);
    }

    gemm_proj<<<dim3(CMODEL / 128, MROWS / 256), 512, gsmem>>>(attn, Wo, out);
}